// round 1
// baseline (speedup 1.0000x reference)
#include <cuda_runtime.h>
#include <cstdint>

#define SEQ   2048
#define BATCH 2
#define DM    1024
#define NH    16
#define DK    64
#define MROWS (BATCH * SEQ)            // 4096
#define OUT_ELEMS ((size_t)BATCH * SEQ * DM)  // 4194304

// Scratch (alloc-free rule: __device__ globals)
__device__ float g_Qp[MROWS * DM];
__device__ float g_Kp[MROWS * DM];
__device__ float g_Vp[MROWS * DM];
__device__ float g_Ctx[MROWS * DM];

__device__ __forceinline__ float neg_inf_f() { return __int_as_float(0xff800000u); }

// ---------------------------------------------------------------------------
// C[M,N] = A[M,K] @ W[N,K]^T + bias[N]   (both operands K-major, "NT" GEMM)
// BM=BN=128, BK=8, 256 threads, 8x8 microtile (split 2x2 of 4x4 for
// conflict-free float4 smem reads).
// ---------------------------------------------------------------------------
__global__ __launch_bounds__(256) void gemm_nt_bias(
    const float* __restrict__ A, const float* __restrict__ W,
    const float* __restrict__ bias, float* __restrict__ C,
    int M, int N, int K)
{
    __shared__ float As[8][128];
    __shared__ float Bs[8][128];
    const int t = threadIdx.x;
    const int rowBase = blockIdx.y * 128;
    const int colBase = blockIdx.x * 128;
    const int ty = t >> 4, tx = t & 15;
    const int lr = t >> 1;          // 0..127
    const int lk = (t & 1) * 4;     // 0 or 4

    const float* Ap = A + (size_t)(rowBase + lr) * K + lk;
    const float* Wp = W + (size_t)(colBase + lr) * K + lk;

    float acc[2][2][4][4];
    #pragma unroll
    for (int i = 0; i < 2; i++)
        #pragma unroll
        for (int j = 0; j < 2; j++)
            #pragma unroll
            for (int ii = 0; ii < 4; ii++)
                #pragma unroll
                for (int jj = 0; jj < 4; jj++) acc[i][j][ii][jj] = 0.0f;

    for (int k0 = 0; k0 < K; k0 += 8) {
        float4 av = *(const float4*)(Ap + k0);
        float4 wv = *(const float4*)(Wp + k0);
        As[lk + 0][lr] = av.x; As[lk + 1][lr] = av.y;
        As[lk + 2][lr] = av.z; As[lk + 3][lr] = av.w;
        Bs[lk + 0][lr] = wv.x; Bs[lk + 1][lr] = wv.y;
        Bs[lk + 2][lr] = wv.z; Bs[lk + 3][lr] = wv.w;
        __syncthreads();
        #pragma unroll
        for (int kk = 0; kk < 8; kk++) {
            float a[2][4], b[2][4];
            *(float4*)a[0] = *(const float4*)&As[kk][ty * 4];
            *(float4*)a[1] = *(const float4*)&As[kk][64 + ty * 4];
            *(float4*)b[0] = *(const float4*)&Bs[kk][tx * 4];
            *(float4*)b[1] = *(const float4*)&Bs[kk][64 + tx * 4];
            #pragma unroll
            for (int i = 0; i < 2; i++)
                #pragma unroll
                for (int ii = 0; ii < 4; ii++) {
                    float avv = a[i][ii];
                    #pragma unroll
                    for (int j = 0; j < 2; j++)
                        #pragma unroll
                        for (int jj = 0; jj < 4; jj++)
                            acc[i][j][ii][jj] += avv * b[j][jj];
                }
        }
        __syncthreads();
    }

    #pragma unroll
    for (int i = 0; i < 2; i++)
        #pragma unroll
        for (int ii = 0; ii < 4; ii++) {
            int r = rowBase + i * 64 + ty * 4 + ii;
            #pragma unroll
            for (int j = 0; j < 2; j++) {
                int c = colBase + j * 64 + tx * 4;
                float4 o;
                o.x = acc[i][j][ii][0] + bias[c + 0];
                o.y = acc[i][j][ii][1] + bias[c + 1];
                o.z = acc[i][j][ii][2] + bias[c + 2];
                o.w = acc[i][j][ii][3] + bias[c + 3];
                *(float4*)&C[(size_t)r * N + c] = o;
            }
        }
}

// ---------------------------------------------------------------------------
// Masked, scaled scores: attn[b,h,q,k] = (Qh . Kh) / 8, or -inf where mask==0.
// 128x128 tile per block, entire D_K=64 kept in smem (dynamic, 64 KB).
// ---------------------------------------------------------------------------
__global__ __launch_bounds__(256) void attn_scores(
    const float* __restrict__ Qp, const float* __restrict__ Kp,
    const int* __restrict__ mask, float* __restrict__ attn)
{
    extern __shared__ float smem[];
    float* Qs = smem;             // [64][128]  (d-major)
    float* Ks = smem + 64 * 128;  // [64][128]

    const int t = threadIdx.x;
    const int bh = blockIdx.z;
    const int b = bh >> 4, h = bh & 15;
    const int qBase = blockIdx.y * 128;
    const int kBase = blockIdx.x * 128;

    const int lr0 = t >> 4;          // 0..15
    const int ld  = (t & 15) * 4;    // 0..60
    const float* qsrc = Qp + ((size_t)(b * SEQ + qBase + lr0)) * DM + h * DK + ld;
    const float* ksrc = Kp + ((size_t)(b * SEQ + kBase + lr0)) * DM + h * DK + ld;
    #pragma unroll
    for (int rr = 0; rr < 128; rr += 16) {
        float4 qv = *(const float4*)(qsrc + (size_t)rr * DM);
        float4 kv = *(const float4*)(ksrc + (size_t)rr * DM);
        int r = lr0 + rr;
        Qs[(ld + 0) * 128 + r] = qv.x; Qs[(ld + 1) * 128 + r] = qv.y;
        Qs[(ld + 2) * 128 + r] = qv.z; Qs[(ld + 3) * 128 + r] = qv.w;
        Ks[(ld + 0) * 128 + r] = kv.x; Ks[(ld + 1) * 128 + r] = kv.y;
        Ks[(ld + 2) * 128 + r] = kv.z; Ks[(ld + 3) * 128 + r] = kv.w;
    }
    __syncthreads();

    const int ty = t >> 4, tx = t & 15;
    float acc[2][2][4][4];
    #pragma unroll
    for (int i = 0; i < 2; i++)
        #pragma unroll
        for (int j = 0; j < 2; j++)
            #pragma unroll
            for (int ii = 0; ii < 4; ii++)
                #pragma unroll
                for (int jj = 0; jj < 4; jj++) acc[i][j][ii][jj] = 0.0f;

    #pragma unroll 4
    for (int d = 0; d < 64; d++) {
        float a[2][4], bb[2][4];
        *(float4*)a[0]  = *(const float4*)&Qs[d * 128 + ty * 4];
        *(float4*)a[1]  = *(const float4*)&Qs[d * 128 + 64 + ty * 4];
        *(float4*)bb[0] = *(const float4*)&Ks[d * 128 + tx * 4];
        *(float4*)bb[1] = *(const float4*)&Ks[d * 128 + 64 + tx * 4];
        #pragma unroll
        for (int i = 0; i < 2; i++)
            #pragma unroll
            for (int ii = 0; ii < 4; ii++) {
                float avv = a[i][ii];
                #pragma unroll
                for (int j = 0; j < 2; j++)
                    #pragma unroll
                    for (int jj = 0; jj < 4; jj++)
                        acc[i][j][ii][jj] += avv * bb[j][jj];
            }
    }

    const float scale = 0.125f;  // 1/sqrt(64)
    #pragma unroll
    for (int i = 0; i < 2; i++)
        #pragma unroll
        for (int ii = 0; ii < 4; ii++) {
            int q = qBase + i * 64 + ty * 4 + ii;
            size_t rowoff = (((size_t)(b * NH + h) * SEQ) + q) * SEQ;
            #pragma unroll
            for (int j = 0; j < 2; j++) {
                int kcol = kBase + j * 64 + tx * 4;
                float4 o;
                o.x = mask[b * SEQ + kcol + 0] ? acc[i][j][ii][0] * scale : neg_inf_f();
                o.y = mask[b * SEQ + kcol + 1] ? acc[i][j][ii][1] * scale : neg_inf_f();
                o.z = mask[b * SEQ + kcol + 2] ? acc[i][j][ii][2] * scale : neg_inf_f();
                o.w = mask[b * SEQ + kcol + 3] ? acc[i][j][ii][3] * scale : neg_inf_f();
                *(float4*)&attn[rowoff + kcol] = o;
            }
        }
}

// ---------------------------------------------------------------------------
// In-place row softmax over attn rows of length 2048. One block per row.
// ---------------------------------------------------------------------------
__global__ __launch_bounds__(256) void softmax_rows(float* __restrict__ attn)
{
    __shared__ float red[8];
    float* p = attn + (size_t)blockIdx.x * SEQ;
    const int t = threadIdx.x;

    float4 v0 = *(const float4*)&p[t * 8];
    float4 v1 = *(const float4*)&p[t * 8 + 4];
    float x[8] = {v0.x, v0.y, v0.z, v0.w, v1.x, v1.y, v1.z, v1.w};

    float m = x[0];
    #pragma unroll
    for (int i = 1; i < 8; i++) m = fmaxf(m, x[i]);
    #pragma unroll
    for (int o = 16; o > 0; o >>= 1) m = fmaxf(m, __shfl_xor_sync(0xffffffffu, m, o));
    if ((t & 31) == 0) red[t >> 5] = m;
    __syncthreads();
    m = red[0];
    #pragma unroll
    for (int i = 1; i < 8; i++) m = fmaxf(m, red[i]);
    __syncthreads();

    float e[8];
    float s = 0.0f;
    #pragma unroll
    for (int i = 0; i < 8; i++) { e[i] = __expf(x[i] - m); s += e[i]; }
    #pragma unroll
    for (int o = 16; o > 0; o >>= 1) s += __shfl_xor_sync(0xffffffffu, s, o);
    if ((t & 31) == 0) red[t >> 5] = s;
    __syncthreads();
    s = red[0];
    #pragma unroll
    for (int i = 1; i < 8; i++) s += red[i];

    float inv = 1.0f / s;
    float4 o0 = make_float4(e[0] * inv, e[1] * inv, e[2] * inv, e[3] * inv);
    float4 o1 = make_float4(e[4] * inv, e[5] * inv, e[6] * inv, e[7] * inv);
    *(float4*)&p[t * 8] = o0;
    *(float4*)&p[t * 8 + 4] = o1;
}

// ---------------------------------------------------------------------------
// Ctx[b,q,h*64+d] = sum_k attn[b,h,q,k] * Vp[b,k,h*64+d]
// BM=128 (q), BN=64 (d), BK=16, 256 threads, 8x4 microtile.
// ---------------------------------------------------------------------------
__global__ __launch_bounds__(256) void attn_pv(
    const float* __restrict__ attn, const float* __restrict__ Vp,
    float* __restrict__ Ctx)
{
    __shared__ float As[16][128];
    __shared__ float Bs[16][68];   // pad to 68 (16B-aligned rows)

    const int t = threadIdx.x;
    const int bh = blockIdx.z;
    const int b = bh >> 4, h = bh & 15;
    const int qBase = blockIdx.y * 128;

    const float* arow = attn + (((size_t)bh * SEQ) + qBase) * SEQ;

    const int ar = t >> 1;          // 0..127 (q row)
    const int ak = (t & 1) * 8;     // 0 or 8
    const int vr = t >> 4;          // 0..15  (k within tile)
    const int vd = (t & 15) * 4;    // 0..60

    const int ty = t >> 4, tx = t & 15;
    float acc[2][4][4];
    #pragma unroll
    for (int i = 0; i < 2; i++)
        #pragma unroll
        for (int ii = 0; ii < 4; ii++)
            #pragma unroll
            for (int jj = 0; jj < 4; jj++) acc[i][ii][jj] = 0.0f;

    for (int k0 = 0; k0 < SEQ; k0 += 16) {
        float4 a0 = *(const float4*)&arow[(size_t)ar * SEQ + k0 + ak];
        float4 a1 = *(const float4*)&arow[(size_t)ar * SEQ + k0 + ak + 4];
        As[ak + 0][ar] = a0.x; As[ak + 1][ar] = a0.y;
        As[ak + 2][ar] = a0.z; As[ak + 3][ar] = a0.w;
        As[ak + 4][ar] = a1.x; As[ak + 5][ar] = a1.y;
        As[ak + 6][ar] = a1.z; As[ak + 7][ar] = a1.w;
        float4 vv = *(const float4*)&Vp[((size_t)(b * SEQ + k0 + vr)) * DM + h * DK + vd];
        *(float4*)&Bs[vr][vd] = vv;
        __syncthreads();
        #pragma unroll
        for (int kk = 0; kk < 16; kk++) {
            float a[2][4], bb[4];
            *(float4*)a[0] = *(const float4*)&As[kk][ty * 4];
            *(float4*)a[1] = *(const float4*)&As[kk][64 + ty * 4];
            *(float4*)bb   = *(const float4*)&Bs[kk][tx * 4];
            #pragma unroll
            for (int i = 0; i < 2; i++)
                #pragma unroll
                for (int ii = 0; ii < 4; ii++) {
                    float avv = a[i][ii];
                    #pragma unroll
                    for (int jj = 0; jj < 4; jj++)
                        acc[i][ii][jj] += avv * bb[jj];
                }
        }
        __syncthreads();
    }

    #pragma unroll
    for (int i = 0; i < 2; i++)
        #pragma unroll
        for (int ii = 0; ii < 4; ii++) {
            int q = qBase + i * 64 + ty * 4 + ii;
            float4 o = make_float4(acc[i][ii][0], acc[i][ii][1],
                                   acc[i][ii][2], acc[i][ii][3]);
            *(float4*)&Ctx[((size_t)(b * SEQ + q)) * DM + h * DK + tx * 4] = o;
        }
}

// ---------------------------------------------------------------------------
extern "C" void kernel_launch(void* const* d_in, const int* in_sizes, int n_in,
                              void* d_out, int out_size)
{
    const float* q    = (const float*)d_in[0];
    const float* k    = (const float*)d_in[1];
    const float* v    = (const float*)d_in[2];
    const int*   mask = (const int*)d_in[3];
    const float* w_q  = (const float*)d_in[4];
    const float* b_q  = (const float*)d_in[5];
    const float* w_v  = (const float*)d_in[6];
    const float* b_v  = (const float*)d_in[7];
    const float* w_o  = (const float*)d_in[8];
    const float* b_o  = (const float*)d_in[9];

    float* out  = (float*)d_out;
    float* attn = out + OUT_ELEMS;

    float *Qp, *Kp, *Vp, *Ctx;
    cudaGetSymbolAddress((void**)&Qp,  g_Qp);
    cudaGetSymbolAddress((void**)&Kp,  g_Kp);
    cudaGetSymbolAddress((void**)&Vp,  g_Vp);
    cudaGetSymbolAddress((void**)&Ctx, g_Ctx);

    cudaFuncSetAttribute(attn_scores, cudaFuncAttributeMaxDynamicSharedMemorySize,
                         64 * 128 * 2 * sizeof(float));

    dim3 gProj(DM / 128, MROWS / 128);   // (8, 32)
    gemm_nt_bias<<<gProj, 256>>>(q, w_q, b_q, Qp, MROWS, DM, DM);
    gemm_nt_bias<<<gProj, 256>>>(k, w_q, b_q, Kp, MROWS, DM, DM);   // K uses w_q (ref)
    gemm_nt_bias<<<gProj, 256>>>(v, w_v, b_v, Vp, MROWS, DM, DM);

    dim3 gScore(SEQ / 128, SEQ / 128, BATCH * NH);   // (16, 16, 32)
    attn_scores<<<gScore, 256, 64 * 128 * 2 * sizeof(float)>>>(Qp, Kp, mask, attn);

    softmax_rows<<<BATCH * NH * SEQ, 256>>>(attn);   // 65536 blocks

    dim3 gPV(1, SEQ / 128, BATCH * NH);              // (1, 16, 32)
    attn_pv<<<gPV, 256>>>(attn, Vp, Ctx);

    gemm_nt_bias<<<gProj, 256>>>(Ctx, w_o, b_o, out, MROWS, DM, DM);
}

// round 3
// speedup vs baseline: 1.1533x; 1.1533x over previous
#include <cuda_runtime.h>
#include <cstdint>

#define SEQ   2048
#define BATCH 2
#define DM    1024
#define NH    16
#define DK    64
#define MROWS (BATCH * SEQ)                   // 4096
#define OUT_ELEMS ((size_t)BATCH * SEQ * DM)  // 4194304

// Scratch (alloc-free rule: __device__ globals)
__device__ float g_Qp[MROWS * DM];
__device__ float g_Kp[MROWS * DM];
__device__ float g_Vp[MROWS * DM];
__device__ float g_Ctx[MROWS * DM];

__device__ __forceinline__ float neg_inf_f() { return __int_as_float(0xff800000u); }

__device__ __forceinline__ uint32_t f2tf32(float x)
{
    uint32_t r;
    asm("cvt.rna.tf32.f32 %0, %1;\n" : "=r"(r) : "f"(x));
    return r;
}

__device__ __forceinline__ void split_tf32(float x, uint32_t& hi, uint32_t& lo)
{
    hi = f2tf32(x);
    lo = f2tf32(x - __uint_as_float(hi));
}

// m16n8k8 TF32 MMA, D += A*B (row.col)
__device__ __forceinline__ void mma_tf32(float4& d, const uint32_t a[4], const uint32_t b[2])
{
    asm volatile(
        "mma.sync.aligned.m16n8k8.row.col.f32.tf32.tf32.f32 "
        "{%0,%1,%2,%3}, {%4,%5,%6,%7}, {%8,%9}, {%0,%1,%2,%3};\n"
        : "+f"(d.x), "+f"(d.y), "+f"(d.z), "+f"(d.w)
        : "r"(a[0]), "r"(a[1]), "r"(a[2]), "r"(a[3]), "r"(b[0]), "r"(b[1]));
}

// 3xTF32 compound: acc += ahi*blo + alo*bhi + ahi*bhi  (~fp32 accuracy)
__device__ __forceinline__ void mma3_tf32(float4& d,
    const uint32_t ahi[4], const uint32_t alo[4],
    const uint32_t bhi[2], const uint32_t blo[2])
{
    mma_tf32(d, ahi, blo);
    mma_tf32(d, alo, bhi);
    mma_tf32(d, ahi, bhi);
}

// ---------------------------------------------------------------------------
// C[M,N] = A[M,K] @ W[N,K]^T + bias[N]   (both K-contiguous, "NT")
// BM=BN=128, BK=32, 256 threads = 8 warps (2M x 4N), warp tile 64x32.
// ---------------------------------------------------------------------------
__global__ __launch_bounds__(256) void gemm_nt_tc(
    const float* __restrict__ A, const float* __restrict__ W,
    const float* __restrict__ bias, float* __restrict__ C,
    int M, int N, int K)
{
    __shared__ float As[128 * 36];
    __shared__ float Bs[128 * 36];
    const int t = threadIdx.x, lane = t & 31, warp = t >> 5;
    const int wm = warp >> 2, wn = warp & 3;
    const int gr = lane >> 2, gc = lane & 3;
    const int rowBase = blockIdx.y * 128, colBase = blockIdx.x * 128;

    float4 acc[4][4] = {};

    for (int k0 = 0; k0 < K; k0 += 32) {
        #pragma unroll
        for (int i = 0; i < 4; i++) {
            int id = t + i * 256;
            int r = id >> 3, c4 = (id & 7) << 2;
            *(float4*)&As[r * 36 + c4] = *(const float4*)&A[(size_t)(rowBase + r) * K + k0 + c4];
            *(float4*)&Bs[r * 36 + c4] = *(const float4*)&W[(size_t)(colBase + r) * K + k0 + c4];
        }
        __syncthreads();
        #pragma unroll
        for (int ks = 0; ks < 4; ks++) {
            const int kb = ks * 8;
            uint32_t ah[4][4], al[4][4], bh[4][2], bl[4][2];
            #pragma unroll
            for (int mi = 0; mi < 4; mi++) {
                int m0 = wm * 64 + mi * 16 + gr;
                split_tf32(As[m0 * 36 + kb + gc],           ah[mi][0], al[mi][0]);
                split_tf32(As[(m0 + 8) * 36 + kb + gc],     ah[mi][1], al[mi][1]);
                split_tf32(As[m0 * 36 + kb + gc + 4],       ah[mi][2], al[mi][2]);
                split_tf32(As[(m0 + 8) * 36 + kb + gc + 4], ah[mi][3], al[mi][3]);
            }
            #pragma unroll
            for (int ni = 0; ni < 4; ni++) {
                int n0 = wn * 32 + ni * 8 + gr;
                split_tf32(Bs[n0 * 36 + kb + gc],     bh[ni][0], bl[ni][0]);
                split_tf32(Bs[n0 * 36 + kb + gc + 4], bh[ni][1], bl[ni][1]);
            }
            #pragma unroll
            for (int mi = 0; mi < 4; mi++)
                #pragma unroll
                for (int ni = 0; ni < 4; ni++)
                    mma3_tf32(acc[mi][ni], ah[mi], al[mi], bh[ni], bl[ni]);
        }
        __syncthreads();
    }

    #pragma unroll
    for (int mi = 0; mi < 4; mi++) {
        int r = rowBase + wm * 64 + mi * 16 + gr;
        #pragma unroll
        for (int ni = 0; ni < 4; ni++) {
            int c = colBase + wn * 32 + ni * 8 + 2 * gc;
            float bx = bias[c], by = bias[c + 1];
            float2 o0 = make_float2(acc[mi][ni].x + bx, acc[mi][ni].y + by);
            float2 o1 = make_float2(acc[mi][ni].z + bx, acc[mi][ni].w + by);
            *(float2*)&C[(size_t)r * N + c] = o0;
            *(float2*)&C[(size_t)(r + 8) * N + c] = o1;
        }
    }
}

// ---------------------------------------------------------------------------
// Scores: attn[b,h,q,k] = (Qh . Kh) * 0.125, or -inf where mask==0.
// 128x128 tile, full D_K=64 in smem (stride 68), 3xTF32 MMA.
// ---------------------------------------------------------------------------
__global__ __launch_bounds__(256) void attn_scores_tc(
    const float* __restrict__ Qp, const float* __restrict__ Kp,
    const int* __restrict__ mask, float* __restrict__ attn)
{
    extern __shared__ float smem[];
    float* Qs = smem;              // [128][68]
    float* Ks = smem + 128 * 68;   // [128][68]

    const int t = threadIdx.x, lane = t & 31, warp = t >> 5;
    const int wm = warp >> 2, wn = warp & 3;
    const int gr = lane >> 2, gc = lane & 3;
    const int bh = blockIdx.z;
    const int b = bh >> 4, h = bh & 15;
    const int qBase = blockIdx.y * 128;
    const int kBase = blockIdx.x * 128;

    #pragma unroll
    for (int i = 0; i < 8; i++) {
        int id = t + i * 256;
        int r = id >> 4, c4 = (id & 15) << 2;
        *(float4*)&Qs[r * 68 + c4] =
            *(const float4*)&Qp[((size_t)(b * SEQ + qBase + r)) * DM + h * DK + c4];
        *(float4*)&Ks[r * 68 + c4] =
            *(const float4*)&Kp[((size_t)(b * SEQ + kBase + r)) * DM + h * DK + c4];
    }
    __syncthreads();

    float4 acc[4][4] = {};
    #pragma unroll
    for (int ks = 0; ks < 8; ks++) {
        const int kb = ks * 8;
        uint32_t ah[4][4], al[4][4], bh2[4][2], bl[4][2];
        #pragma unroll
        for (int mi = 0; mi < 4; mi++) {
            int m0 = wm * 64 + mi * 16 + gr;
            split_tf32(Qs[m0 * 68 + kb + gc],           ah[mi][0], al[mi][0]);
            split_tf32(Qs[(m0 + 8) * 68 + kb + gc],     ah[mi][1], al[mi][1]);
            split_tf32(Qs[m0 * 68 + kb + gc + 4],       ah[mi][2], al[mi][2]);
            split_tf32(Qs[(m0 + 8) * 68 + kb + gc + 4], ah[mi][3], al[mi][3]);
        }
        #pragma unroll
        for (int ni = 0; ni < 4; ni++) {
            int n0 = wn * 32 + ni * 8 + gr;
            split_tf32(Ks[n0 * 68 + kb + gc],     bh2[ni][0], bl[ni][0]);
            split_tf32(Ks[n0 * 68 + kb + gc + 4], bh2[ni][1], bl[ni][1]);
        }
        #pragma unroll
        for (int mi = 0; mi < 4; mi++)
            #pragma unroll
            for (int ni = 0; ni < 4; ni++)
                mma3_tf32(acc[mi][ni], ah[mi], al[mi], bh2[ni], bl[ni]);
    }

    const float scale = 0.125f;
    #pragma unroll
    for (int mi = 0; mi < 4; mi++) {
        int q = qBase + wm * 64 + mi * 16 + gr;
        size_t row0 = ((size_t)bh * SEQ + q) * SEQ;
        size_t row1 = ((size_t)bh * SEQ + q + 8) * SEQ;
        #pragma unroll
        for (int ni = 0; ni < 4; ni++) {
            int c = kBase + wn * 32 + ni * 8 + 2 * gc;
            int m0 = mask[b * SEQ + c], m1 = mask[b * SEQ + c + 1];
            float2 o0, o1;
            o0.x = m0 ? acc[mi][ni].x * scale : neg_inf_f();
            o0.y = m1 ? acc[mi][ni].y * scale : neg_inf_f();
            o1.x = m0 ? acc[mi][ni].z * scale : neg_inf_f();
            o1.y = m1 ? acc[mi][ni].w * scale : neg_inf_f();
            *(float2*)&attn[row0 + c] = o0;
            *(float2*)&attn[row1 + c] = o1;
        }
    }
}

// ---------------------------------------------------------------------------
// In-place row softmax over rows of length 2048. One block per row.
// ---------------------------------------------------------------------------
__global__ __launch_bounds__(256) void softmax_rows(float* __restrict__ attn)
{
    __shared__ float red[8];
    float* p = attn + (size_t)blockIdx.x * SEQ;
    const int t = threadIdx.x;

    float4 v0 = *(const float4*)&p[t * 8];
    float4 v1 = *(const float4*)&p[t * 8 + 4];
    float x[8] = {v0.x, v0.y, v0.z, v0.w, v1.x, v1.y, v1.z, v1.w};

    float m = x[0];
    #pragma unroll
    for (int i = 1; i < 8; i++) m = fmaxf(m, x[i]);
    #pragma unroll
    for (int o = 16; o > 0; o >>= 1) m = fmaxf(m, __shfl_xor_sync(0xffffffffu, m, o));
    if ((t & 31) == 0) red[t >> 5] = m;
    __syncthreads();
    m = red[0];
    #pragma unroll
    for (int i = 1; i < 8; i++) m = fmaxf(m, red[i]);
    __syncthreads();

    float e[8];
    float s = 0.0f;
    #pragma unroll
    for (int i = 0; i < 8; i++) { e[i] = __expf(x[i] - m); s += e[i]; }
    #pragma unroll
    for (int o = 16; o > 0; o >>= 1) s += __shfl_xor_sync(0xffffffffu, s, o);
    if ((t & 31) == 0) red[t >> 5] = s;
    __syncthreads();
    s = red[0];
    #pragma unroll
    for (int i = 1; i < 8; i++) s += red[i];

    float inv = 1.0f / s;
    float4 o0 = make_float4(e[0] * inv, e[1] * inv, e[2] * inv, e[3] * inv);
    float4 o1 = make_float4(e[4] * inv, e[5] * inv, e[6] * inv, e[7] * inv);
    *(float4*)&p[t * 8] = o0;
    *(float4*)&p[t * 8 + 4] = o1;
}

// ---------------------------------------------------------------------------
// Ctx[b,q,h*64+d] = sum_k attn[b,h,q,k] * Vp[b,k,h*64+d]
// BM=128 (q), BN=64 (d), BK=32, 8 warps (2M x 4N), warp tile 64x16, 3xTF32.
// ---------------------------------------------------------------------------
__global__ __launch_bounds__(256) void attn_pv_tc(
    const float* __restrict__ attn, const float* __restrict__ Vp,
    float* __restrict__ Ctx)
{
    __shared__ float Ps[128 * 36];
    __shared__ float Vs[64 * 33];

    const int t = threadIdx.x, lane = t & 31, warp = t >> 5;
    const int wm = warp >> 2, wn = warp & 3;
    const int gr = lane >> 2, gc = lane & 3;
    const int bh = blockIdx.z;
    const int b = bh >> 4, h = bh & 15;
    const int qBase = blockIdx.y * 128;

    const float* arow = attn + ((size_t)bh * SEQ + qBase) * SEQ;

    float4 acc[4][2] = {};

    for (int k0 = 0; k0 < SEQ; k0 += 32) {
        #pragma unroll
        for (int i = 0; i < 4; i++) {
            int id = t + i * 256;
            int r = id >> 3, c4 = (id & 7) << 2;
            *(float4*)&Ps[r * 36 + c4] = *(const float4*)&arow[(size_t)r * SEQ + k0 + c4];
        }
        #pragma unroll
        for (int i = 0; i < 2; i++) {
            int id = t + i * 256;
            int kr = id >> 4, d4 = (id & 15) << 2;
            float4 vv = *(const float4*)&Vp[((size_t)(b * SEQ + k0 + kr)) * DM + h * DK + d4];
            Vs[(d4 + 0) * 33 + kr] = vv.x;
            Vs[(d4 + 1) * 33 + kr] = vv.y;
            Vs[(d4 + 2) * 33 + kr] = vv.z;
            Vs[(d4 + 3) * 33 + kr] = vv.w;
        }
        __syncthreads();
        #pragma unroll
        for (int ks = 0; ks < 4; ks++) {
            const int kb = ks * 8;
            uint32_t ah[4][4], al[4][4], bh2[2][2], bl[2][2];
            #pragma unroll
            for (int mi = 0; mi < 4; mi++) {
                int m0 = wm * 64 + mi * 16 + gr;
                split_tf32(Ps[m0 * 36 + kb + gc],           ah[mi][0], al[mi][0]);
                split_tf32(Ps[(m0 + 8) * 36 + kb + gc],     ah[mi][1], al[mi][1]);
                split_tf32(Ps[m0 * 36 + kb + gc + 4],       ah[mi][2], al[mi][2]);
                split_tf32(Ps[(m0 + 8) * 36 + kb + gc + 4], ah[mi][3], al[mi][3]);
            }
            #pragma unroll
            for (int ni = 0; ni < 2; ni++) {
                int n0 = wn * 16 + ni * 8 + gr;
                split_tf32(Vs[n0 * 33 + kb + gc],     bh2[ni][0], bl[ni][0]);
                split_tf32(Vs[n0 * 33 + kb + gc + 4], bh2[ni][1], bl[ni][1]);
            }
            #pragma unroll
            for (int mi = 0; mi < 4; mi++)
                #pragma unroll
                for (int ni = 0; ni < 2; ni++)
                    mma3_tf32(acc[mi][ni], ah[mi], al[mi], bh2[ni], bl[ni]);
        }
        __syncthreads();
    }

    #pragma unroll
    for (int mi = 0; mi < 4; mi++) {
        int q = qBase + wm * 64 + mi * 16 + gr;
        #pragma unroll
        for (int ni = 0; ni < 2; ni++) {
            int c = wn * 16 + ni * 8 + 2 * gc;
            float2 o0 = make_float2(acc[mi][ni].x, acc[mi][ni].y);
            float2 o1 = make_float2(acc[mi][ni].z, acc[mi][ni].w);
            *(float2*)&Ctx[((size_t)(b * SEQ + q)) * DM + h * DK + c] = o0;
            *(float2*)&Ctx[((size_t)(b * SEQ + q + 8)) * DM + h * DK + c] = o1;
        }
    }
}

// ---------------------------------------------------------------------------
extern "C" void kernel_launch(void* const* d_in, const int* in_sizes, int n_in,
                              void* d_out, int out_size)
{
    const float* q    = (const float*)d_in[0];
    const float* k    = (const float*)d_in[1];
    const float* v    = (const float*)d_in[2];
    const int*   mask = (const int*)d_in[3];
    const float* w_q  = (const float*)d_in[4];
    const float* b_q  = (const float*)d_in[5];
    const float* w_v  = (const float*)d_in[6];
    const float* b_v  = (const float*)d_in[7];
    const float* w_o  = (const float*)d_in[8];
    const float* b_o  = (const float*)d_in[9];

    float* out  = (float*)d_out;
    float* attn = out + OUT_ELEMS;

    float *Qp, *Kp, *Vp, *Ctx;
    cudaGetSymbolAddress((void**)&Qp,  g_Qp);
    cudaGetSymbolAddress((void**)&Kp,  g_Kp);
    cudaGetSymbolAddress((void**)&Vp,  g_Vp);
    cudaGetSymbolAddress((void**)&Ctx, g_Ctx);

    static bool attr_set = false;
    if (!attr_set) {
        cudaFuncSetAttribute(attn_scores_tc, cudaFuncAttributeMaxDynamicSharedMemorySize,
                             2 * 128 * 68 * sizeof(float));
        attr_set = true;
    }

    dim3 gProj(DM / 128, MROWS / 128);   // (8, 32)
    gemm_nt_tc<<<gProj, 256>>>(q, w_q, b_q, Qp, MROWS, DM, DM);
    gemm_nt_tc<<<gProj, 256>>>(k, w_q, b_q, Kp, MROWS, DM, DM);   // K uses w_q (ref)
    gemm_nt_tc<<<gProj, 256>>>(v, w_v, b_v, Vp, MROWS, DM, DM);

    dim3 gScore(SEQ / 128, SEQ / 128, BATCH * NH);   // (16, 16, 32)
    attn_scores_tc<<<gScore, 256, 2 * 128 * 68 * sizeof(float)>>>(Qp, Kp, mask, attn);

    softmax_rows<<<BATCH * NH * SEQ, 256>>>(attn);   // 65536 blocks

    dim3 gPV(1, SEQ / 128, BATCH * NH);              // (1, 16, 32)
    attn_pv_tc<<<gPV, 256>>>(attn, Vp, Ctx);

    gemm_nt_tc<<<gProj, 256>>>(Ctx, w_o, b_o, out, MROWS, DM, DM);
}

// round 5
// speedup vs baseline: 1.4368x; 1.2459x over previous
#include <cuda_runtime.h>
#include <cuda_bf16.h>
#include <cstdint>

#define SEQ   2048
#define BATCH 2
#define DM    1024
#define NH    16
#define DK    64
#define MROWS (BATCH * SEQ)                   // 4096
#define OUT_ELEMS ((size_t)BATCH * SEQ * DM)  // 4194304

typedef __nv_bfloat16 bf16;

// -------- device scratch (alloc-free rule) --------
__device__ bf16 g_qhi[MROWS * DM], g_qlo[MROWS * DM];
__device__ bf16 g_khi[MROWS * DM], g_klo[MROWS * DM];
__device__ bf16 g_vhi[MROWS * DM], g_vlo[MROWS * DM];
__device__ bf16 g_wqhi[DM * DM],  g_wqlo[DM * DM];
__device__ bf16 g_wvhi[DM * DM],  g_wvlo[DM * DM];
__device__ bf16 g_wohi[DM * DM],  g_wolo[DM * DM];
__device__ bf16 g_Qhi[MROWS * DM], g_Qlo[MROWS * DM];
__device__ bf16 g_Khi[MROWS * DM], g_Klo[MROWS * DM];
__device__ bf16 g_Vthi[MROWS * DM], g_Vtlo[MROWS * DM];  // [b][dm_col][tok]
__device__ bf16 g_Chi[MROWS * DM], g_Clo[MROWS * DM];

__device__ __forceinline__ float neg_inf_f() { return __int_as_float(0xff800000u); }

__device__ __forceinline__ void bsplit(float x, bf16& h, bf16& l)
{
    h = __float2bfloat16(x);
    l = __float2bfloat16(x - __bfloat162float(h));
}

// m16n8k16 BF16 MMA, D += A*B (row.col)
__device__ __forceinline__ void mma_bf16(float4& d,
    uint32_t a0, uint32_t a1, uint32_t a2, uint32_t a3, uint32_t b0, uint32_t b1)
{
    asm volatile(
        "mma.sync.aligned.m16n8k16.row.col.f32.bf16.bf16.f32 "
        "{%0,%1,%2,%3}, {%4,%5,%6,%7}, {%8,%9}, {%0,%1,%2,%3};\n"
        : "+f"(d.x), "+f"(d.y), "+f"(d.z), "+f"(d.w)
        : "r"(a0), "r"(a1), "r"(a2), "r"(a3), "r"(b0), "r"(b1));
}

// ---------------------------------------------------------------------------
// Elementwise split: f32 -> bf16 hi/lo planes. n multiple of 4.
// ---------------------------------------------------------------------------
__global__ __launch_bounds__(256) void split_kernel(
    const float* __restrict__ x, bf16* __restrict__ hi, bf16* __restrict__ lo, int n4)
{
    int i = blockIdx.x * 256 + threadIdx.x;
    if (i >= n4) return;
    float4 v = ((const float4*)x)[i];
    bf16 h0, l0, h1, l1, h2, l2, h3, l3;
    bsplit(v.x, h0, l0); bsplit(v.y, h1, l1);
    bsplit(v.z, h2, l2); bsplit(v.w, h3, l3);
    ((__nv_bfloat162*)hi)[2 * i]     = __nv_bfloat162(h0, h1);
    ((__nv_bfloat162*)hi)[2 * i + 1] = __nv_bfloat162(h2, h3);
    ((__nv_bfloat162*)lo)[2 * i]     = __nv_bfloat162(l0, l1);
    ((__nv_bfloat162*)lo)[2 * i + 1] = __nv_bfloat162(l2, l3);
}

// ---------------------------------------------------------------------------
// C[M,N] = A[M,K] @ W[N,K]^T + bias[N], operands pre-split bf16 hi/lo planes.
// BM=BN=128, BK=64, 8 warps (2Mx4N), warp tile 64x32, 3xBF16 MMA.
// mode 0: write f32 C. mode 1: write Chi/Clo planes. mode 2: write transposed
// V planes Ct[(b*DM + col)*SEQ + tok].
// ---------------------------------------------------------------------------
__global__ __launch_bounds__(256) void gemm_bf3(
    const bf16* __restrict__ Ahi, const bf16* __restrict__ Alo,
    const bf16* __restrict__ Whi, const bf16* __restrict__ Wlo,
    const float* __restrict__ bias, int M, int N, int K,
    int mode, float* __restrict__ Cf, bf16* __restrict__ Chi, bf16* __restrict__ Clo)
{
    extern __shared__ bf16 smg[];
    bf16* sAhi = smg;                 // 128 x 72
    bf16* sAlo = sAhi + 128 * 72;
    bf16* sBhi = sAlo + 128 * 72;
    bf16* sBlo = sBhi + 128 * 72;

    const int t = threadIdx.x, lane = t & 31, warp = t >> 5;
    const int wm = warp >> 2, wn = warp & 3;
    const int gr = lane >> 2, gc = lane & 3;
    const int rowBase = blockIdx.y * 128, colBase = blockIdx.x * 128;

    float4 acc[4][4] = {};

    for (int k0 = 0; k0 < K; k0 += 64) {
        #pragma unroll
        for (int i = 0; i < 4; i++) {
            int id = t + i * 256;
            int r = id >> 3, c = id & 7;
            *(float4*)&sAhi[r * 72 + c * 8] = *(const float4*)&Ahi[(size_t)(rowBase + r) * K + k0 + c * 8];
            *(float4*)&sAlo[r * 72 + c * 8] = *(const float4*)&Alo[(size_t)(rowBase + r) * K + k0 + c * 8];
            *(float4*)&sBhi[r * 72 + c * 8] = *(const float4*)&Whi[(size_t)(colBase + r) * K + k0 + c * 8];
            *(float4*)&sBlo[r * 72 + c * 8] = *(const float4*)&Wlo[(size_t)(colBase + r) * K + k0 + c * 8];
        }
        __syncthreads();
        #pragma unroll
        for (int ks = 0; ks < 4; ks++) {
            const int kb = ks * 16;
            uint32_t ah[4][4], al[4][4];
            #pragma unroll
            for (int mi = 0; mi < 4; mi++) {
                int m0 = (wm * 64 + mi * 16 + gr) * 72 + kb + 2 * gc;
                ah[mi][0] = *(const uint32_t*)&sAhi[m0];
                ah[mi][1] = *(const uint32_t*)&sAhi[m0 + 8 * 72];
                ah[mi][2] = *(const uint32_t*)&sAhi[m0 + 8];
                ah[mi][3] = *(const uint32_t*)&sAhi[m0 + 8 * 72 + 8];
                al[mi][0] = *(const uint32_t*)&sAlo[m0];
                al[mi][1] = *(const uint32_t*)&sAlo[m0 + 8 * 72];
                al[mi][2] = *(const uint32_t*)&sAlo[m0 + 8];
                al[mi][3] = *(const uint32_t*)&sAlo[m0 + 8 * 72 + 8];
            }
            #pragma unroll
            for (int ni = 0; ni < 4; ni++) {
                int n0 = (wn * 32 + ni * 8 + gr) * 72 + kb + 2 * gc;
                uint32_t bh0 = *(const uint32_t*)&sBhi[n0];
                uint32_t bh1 = *(const uint32_t*)&sBhi[n0 + 8];
                uint32_t bl0 = *(const uint32_t*)&sBlo[n0];
                uint32_t bl1 = *(const uint32_t*)&sBlo[n0 + 8];
                #pragma unroll
                for (int mi = 0; mi < 4; mi++) {
                    mma_bf16(acc[mi][ni], ah[mi][0], ah[mi][1], ah[mi][2], ah[mi][3], bl0, bl1);
                    mma_bf16(acc[mi][ni], al[mi][0], al[mi][1], al[mi][2], al[mi][3], bh0, bh1);
                    mma_bf16(acc[mi][ni], ah[mi][0], ah[mi][1], ah[mi][2], ah[mi][3], bh0, bh1);
                }
            }
        }
        __syncthreads();
    }

    #pragma unroll
    for (int mi = 0; mi < 4; mi++) {
        int r = rowBase + wm * 64 + mi * 16 + gr;
        #pragma unroll
        for (int ni = 0; ni < 4; ni++) {
            int c = colBase + wn * 32 + ni * 8 + 2 * gc;
            float bx = bias[c], by = bias[c + 1];
            float x0 = acc[mi][ni].x + bx, y0 = acc[mi][ni].y + by;
            float z0 = acc[mi][ni].z + bx, w0 = acc[mi][ni].w + by;
            if (mode == 0) {
                *(float2*)&Cf[(size_t)r * N + c]       = make_float2(x0, y0);
                *(float2*)&Cf[(size_t)(r + 8) * N + c] = make_float2(z0, w0);
            } else if (mode == 1) {
                bf16 h0, l0, h1, l1, h2, l2, h3, l3;
                bsplit(x0, h0, l0); bsplit(y0, h1, l1);
                bsplit(z0, h2, l2); bsplit(w0, h3, l3);
                *(__nv_bfloat162*)&Chi[(size_t)r * N + c]       = __nv_bfloat162(h0, h1);
                *(__nv_bfloat162*)&Clo[(size_t)r * N + c]       = __nv_bfloat162(l0, l1);
                *(__nv_bfloat162*)&Chi[(size_t)(r + 8) * N + c] = __nv_bfloat162(h2, h3);
                *(__nv_bfloat162*)&Clo[(size_t)(r + 8) * N + c] = __nv_bfloat162(l2, l3);
            } else {
                // transposed: Ct[(b*DM + c)*SEQ + tok]
                int bidx = r >> 11, tok = r & 2047;
                size_t base = ((size_t)bidx * DM + c) * SEQ + tok;
                bf16 h, l;
                bsplit(x0, h, l); Chi[base] = h;            Clo[base] = l;
                bsplit(y0, h, l); Chi[base + SEQ] = h;      Clo[base + SEQ] = l;
                bsplit(z0, h, l); Chi[base + 8] = h;        Clo[base + 8] = l;
                bsplit(w0, h, l); Chi[base + SEQ + 8] = h;  Clo[base + SEQ + 8] = l;
            }
        }
    }
}

// ---------------------------------------------------------------------------
// Scores: attn[b,h,q,k] = (Qh.Kh)*0.125 or -inf (mask==0). 3xBF16 MMA.
// ---------------------------------------------------------------------------
__global__ __launch_bounds__(256) void attn_scores_bf(
    const bf16* __restrict__ Qhi, const bf16* __restrict__ Qlo,
    const bf16* __restrict__ Khi, const bf16* __restrict__ Klo,
    const int* __restrict__ mask, float* __restrict__ attn)
{
    extern __shared__ bf16 sms[];
    bf16* sQhi = sms;                // 128 x 72
    bf16* sQlo = sQhi + 128 * 72;
    bf16* sKhi = sQlo + 128 * 72;
    bf16* sKlo = sKhi + 128 * 72;

    const int t = threadIdx.x, lane = t & 31, warp = t >> 5;
    const int wm = warp >> 2, wn = warp & 3;
    const int gr = lane >> 2, gc = lane & 3;
    const int bh = blockIdx.z;
    const int b = bh >> 4, h = bh & 15;
    const int qBase = blockIdx.y * 128;
    const int kBase = blockIdx.x * 128;

    #pragma unroll
    for (int i = 0; i < 4; i++) {
        int id = t + i * 256;
        int r = id >> 3, c = id & 7;
        size_t qoff = (size_t)(b * SEQ + qBase + r) * DM + h * DK + c * 8;
        size_t koff = (size_t)(b * SEQ + kBase + r) * DM + h * DK + c * 8;
        *(float4*)&sQhi[r * 72 + c * 8] = *(const float4*)&Qhi[qoff];
        *(float4*)&sQlo[r * 72 + c * 8] = *(const float4*)&Qlo[qoff];
        *(float4*)&sKhi[r * 72 + c * 8] = *(const float4*)&Khi[koff];
        *(float4*)&sKlo[r * 72 + c * 8] = *(const float4*)&Klo[koff];
    }
    __syncthreads();

    float4 acc[4][4] = {};
    #pragma unroll
    for (int ks = 0; ks < 4; ks++) {
        const int kb = ks * 16;
        uint32_t ah[4][4], al[4][4];
        #pragma unroll
        for (int mi = 0; mi < 4; mi++) {
            int m0 = (wm * 64 + mi * 16 + gr) * 72 + kb + 2 * gc;
            ah[mi][0] = *(const uint32_t*)&sQhi[m0];
            ah[mi][1] = *(const uint32_t*)&sQhi[m0 + 8 * 72];
            ah[mi][2] = *(const uint32_t*)&sQhi[m0 + 8];
            ah[mi][3] = *(const uint32_t*)&sQhi[m0 + 8 * 72 + 8];
            al[mi][0] = *(const uint32_t*)&sQlo[m0];
            al[mi][1] = *(const uint32_t*)&sQlo[m0 + 8 * 72];
            al[mi][2] = *(const uint32_t*)&sQlo[m0 + 8];
            al[mi][3] = *(const uint32_t*)&sQlo[m0 + 8 * 72 + 8];
        }
        #pragma unroll
        for (int ni = 0; ni < 4; ni++) {
            int n0 = (wn * 32 + ni * 8 + gr) * 72 + kb + 2 * gc;
            uint32_t bh0 = *(const uint32_t*)&sKhi[n0];
            uint32_t bh1 = *(const uint32_t*)&sKhi[n0 + 8];
            uint32_t bl0 = *(const uint32_t*)&sKlo[n0];
            uint32_t bl1 = *(const uint32_t*)&sKlo[n0 + 8];
            #pragma unroll
            for (int mi = 0; mi < 4; mi++) {
                mma_bf16(acc[mi][ni], ah[mi][0], ah[mi][1], ah[mi][2], ah[mi][3], bl0, bl1);
                mma_bf16(acc[mi][ni], al[mi][0], al[mi][1], al[mi][2], al[mi][3], bh0, bh1);
                mma_bf16(acc[mi][ni], ah[mi][0], ah[mi][1], ah[mi][2], ah[mi][3], bh0, bh1);
            }
        }
    }

    const float scale = 0.125f;
    #pragma unroll
    for (int mi = 0; mi < 4; mi++) {
        int q = qBase + wm * 64 + mi * 16 + gr;
        size_t row0 = ((size_t)bh * SEQ + q) * SEQ;
        size_t row1 = row0 + (size_t)8 * SEQ;
        #pragma unroll
        for (int ni = 0; ni < 4; ni++) {
            int c = kBase + wn * 32 + ni * 8 + 2 * gc;
            int m0 = mask[b * SEQ + c], m1 = mask[b * SEQ + c + 1];
            float2 o0, o1;
            o0.x = m0 ? acc[mi][ni].x * scale : neg_inf_f();
            o0.y = m1 ? acc[mi][ni].y * scale : neg_inf_f();
            o1.x = m0 ? acc[mi][ni].z * scale : neg_inf_f();
            o1.y = m1 ? acc[mi][ni].w * scale : neg_inf_f();
            *(float2*)&attn[row0 + c] = o0;
            *(float2*)&attn[row1 + c] = o1;
        }
    }
}

// ---------------------------------------------------------------------------
// Fused softmax + PV. Block = (qtile 128, bh). Phase 1: online row max/sum.
// Phase 2: per 128-col ktile: normalize, write attn in place, P->smem bf16
// split, 3xBF16 MMA with transposed V planes. Epilogue: Ctx hi/lo planes.
// ---------------------------------------------------------------------------
__global__ __launch_bounds__(256) void softmax_pv_bf(
    float* __restrict__ attn,
    const bf16* __restrict__ Vthi, const bf16* __restrict__ Vtlo,
    bf16* __restrict__ Chi, bf16* __restrict__ Clo)
{
    extern __shared__ unsigned char smraw[];
    float* sm_m   = (float*)smraw;           // 128
    float* sm_inv = sm_m + 128;               // 128
    bf16* sPhi = (bf16*)(sm_inv + 128);       // 128 x 136
    bf16* sPlo = sPhi + 128 * 136;
    bf16* sVhi = sPlo + 128 * 136;            // 64 x 136
    bf16* sVlo = sVhi + 64 * 136;

    const int t = threadIdx.x, lane = t & 31, warp = t >> 5;
    const int gr = lane >> 2, gc = lane & 3;
    const int wm = warp >> 2, wn = warp & 3;
    const int qBase = blockIdx.x * 128;
    const int bh = blockIdx.y;
    const int b = bh >> 4, h = bh & 15;

    float* ablk = attn + ((size_t)bh * SEQ + qBase) * SEQ;

    // ---- phase 1: row max + sum (online) ----
    for (int j = 0; j < 16; j++) {
        int r = warp * 16 + j;
        const float4* p4 = (const float4*)(ablk + (size_t)r * SEQ);
        float m = -1e30f, s = 0.0f;
        for (int c = lane; c < 512; c += 32) {
            float4 v = p4[c];
            float mx = fmaxf(fmaxf(v.x, v.y), fmaxf(v.z, v.w));
            if (mx > m) { s *= __expf(m - mx); m = mx; }
            s += __expf(v.x - m) + __expf(v.y - m) + __expf(v.z - m) + __expf(v.w - m);
        }
        #pragma unroll
        for (int o = 16; o > 0; o >>= 1) {
            float m2 = __shfl_xor_sync(0xffffffffu, m, o);
            float s2 = __shfl_xor_sync(0xffffffffu, s, o);
            float mn = fmaxf(m, m2);
            s = s * __expf(m - mn) + s2 * __expf(m2 - mn);
            m = mn;
        }
        if (lane == 0) { sm_m[r] = m; sm_inv[r] = 1.0f / s; }
    }
    __syncthreads();

    // ---- phase 2 ----
    const int pr = t >> 1, ho = (t & 1) * 64;   // this thread's P row / col-half
    const float mr = sm_m[pr];
    const float ir = sm_inv[pr];

    float4 acc[4][2] = {};

    for (int kt = 0; kt < 16; kt++) {
        // load transposed V tile: 64 d-rows x 128 toks (full width!)
        #pragma unroll
        for (int i = 0; i < 4; i++) {
            int id = t + i * 256;
            int d = id >> 4, c = id & 15;
            size_t off = ((size_t)b * DM + h * DK + d) * SEQ + kt * 128 + c * 8;
            *(float4*)&sVhi[d * 136 + c * 8] = *(const float4*)&Vthi[off];
            *(float4*)&sVlo[d * 136 + c * 8] = *(const float4*)&Vtlo[off];
        }
        // normalize P tile, write attn, stage bf16 split into smem
        float* prow = ablk + (size_t)pr * SEQ + kt * 128 + ho;
        #pragma unroll
        for (int i = 0; i < 16; i++) {
            float4 v = *(const float4*)&prow[i * 4];
            float4 p;
            p.x = __expf(v.x - mr) * ir;
            p.y = __expf(v.y - mr) * ir;
            p.z = __expf(v.z - mr) * ir;
            p.w = __expf(v.w - mr) * ir;
            *(float4*)&prow[i * 4] = p;
            bf16 h0, l0, h1, l1, h2, l2, h3, l3;
            bsplit(p.x, h0, l0); bsplit(p.y, h1, l1);
            bsplit(p.z, h2, l2); bsplit(p.w, h3, l3);
            int widx = pr * 136 + ho + i * 4;
            *(__nv_bfloat162*)&sPhi[widx]     = __nv_bfloat162(h0, h1);
            *(__nv_bfloat162*)&sPhi[widx + 2] = __nv_bfloat162(h2, h3);
            *(__nv_bfloat162*)&sPlo[widx]     = __nv_bfloat162(l0, l1);
            *(__nv_bfloat162*)&sPlo[widx + 2] = __nv_bfloat162(l2, l3);
        }
        __syncthreads();
        // PV MMA: warp tile m64 x n16
        #pragma unroll
        for (int ks = 0; ks < 8; ks++) {
            const int kb = ks * 16;
            uint32_t ah[4][4], al[4][4];
            #pragma unroll
            for (int mi = 0; mi < 4; mi++) {
                int m0 = (wm * 64 + mi * 16 + gr) * 136 + kb + 2 * gc;
                ah[mi][0] = *(const uint32_t*)&sPhi[m0];
                ah[mi][1] = *(const uint32_t*)&sPhi[m0 + 8 * 136];
                ah[mi][2] = *(const uint32_t*)&sPhi[m0 + 8];
                ah[mi][3] = *(const uint32_t*)&sPhi[m0 + 8 * 136 + 8];
                al[mi][0] = *(const uint32_t*)&sPlo[m0];
                al[mi][1] = *(const uint32_t*)&sPlo[m0 + 8 * 136];
                al[mi][2] = *(const uint32_t*)&sPlo[m0 + 8];
                al[mi][3] = *(const uint32_t*)&sPlo[m0 + 8 * 136 + 8];
            }
            #pragma unroll
            for (int ni = 0; ni < 2; ni++) {
                int n0 = (wn * 16 + ni * 8 + gr) * 136 + kb + 2 * gc;
                uint32_t bh0 = *(const uint32_t*)&sVhi[n0];
                uint32_t bh1 = *(const uint32_t*)&sVhi[n0 + 8];
                uint32_t bl0 = *(const uint32_t*)&sVlo[n0];
                uint32_t bl1 = *(const uint32_t*)&sVlo[n0 + 8];
                #pragma unroll
                for (int mi = 0; mi < 4; mi++) {
                    mma_bf16(acc[mi][ni], ah[mi][0], ah[mi][1], ah[mi][2], ah[mi][3], bl0, bl1);
                    mma_bf16(acc[mi][ni], al[mi][0], al[mi][1], al[mi][2], al[mi][3], bh0, bh1);
                    mma_bf16(acc[mi][ni], ah[mi][0], ah[mi][1], ah[mi][2], ah[mi][3], bh0, bh1);
                }
            }
        }
        __syncthreads();
    }

    // epilogue: Ctx hi/lo planes [token][DM]
    #pragma unroll
    for (int mi = 0; mi < 4; mi++) {
        int q = qBase + wm * 64 + mi * 16 + gr;
        #pragma unroll
        for (int ni = 0; ni < 2; ni++) {
            int d = wn * 16 + ni * 8 + 2 * gc;
            size_t o0 = (size_t)(b * SEQ + q) * DM + h * DK + d;
            size_t o1 = o0 + (size_t)8 * DM;
            bf16 h0, l0, h1, l1;
            bsplit(acc[mi][ni].x, h0, l0); bsplit(acc[mi][ni].y, h1, l1);
            *(__nv_bfloat162*)&Chi[o0] = __nv_bfloat162(h0, h1);
            *(__nv_bfloat162*)&Clo[o0] = __nv_bfloat162(l0, l1);
            bsplit(acc[mi][ni].z, h0, l0); bsplit(acc[mi][ni].w, h1, l1);
            *(__nv_bfloat162*)&Chi[o1] = __nv_bfloat162(h0, h1);
            *(__nv_bfloat162*)&Clo[o1] = __nv_bfloat162(l0, l1);
        }
    }
}

// ---------------------------------------------------------------------------
extern "C" void kernel_launch(void* const* d_in, const int* in_sizes, int n_in,
                              void* d_out, int out_size)
{
    const float* q    = (const float*)d_in[0];
    const float* k    = (const float*)d_in[1];
    const float* v    = (const float*)d_in[2];
    const int*   mask = (const int*)d_in[3];
    const float* w_q  = (const float*)d_in[4];
    const float* b_q  = (const float*)d_in[5];
    const float* w_v  = (const float*)d_in[6];
    const float* b_v  = (const float*)d_in[7];
    const float* w_o  = (const float*)d_in[8];
    const float* b_o  = (const float*)d_in[9];

    float* out  = (float*)d_out;
    float* attn = out + OUT_ELEMS;

    bf16 *qhi, *qlo, *khi, *klo, *vhi, *vlo;
    bf16 *wqhi, *wqlo, *wvhi, *wvlo, *wohi, *wolo;
    bf16 *Qhi, *Qlo, *Khi, *Klo, *Vthi, *Vtlo, *Chi, *Clo;
    cudaGetSymbolAddress((void**)&qhi, g_qhi);   cudaGetSymbolAddress((void**)&qlo, g_qlo);
    cudaGetSymbolAddress((void**)&khi, g_khi);   cudaGetSymbolAddress((void**)&klo, g_klo);
    cudaGetSymbolAddress((void**)&vhi, g_vhi);   cudaGetSymbolAddress((void**)&vlo, g_vlo);
    cudaGetSymbolAddress((void**)&wqhi, g_wqhi); cudaGetSymbolAddress((void**)&wqlo, g_wqlo);
    cudaGetSymbolAddress((void**)&wvhi, g_wvhi); cudaGetSymbolAddress((void**)&wvlo, g_wvlo);
    cudaGetSymbolAddress((void**)&wohi, g_wohi); cudaGetSymbolAddress((void**)&wolo, g_wolo);
    cudaGetSymbolAddress((void**)&Qhi, g_Qhi);   cudaGetSymbolAddress((void**)&Qlo, g_Qlo);
    cudaGetSymbolAddress((void**)&Khi, g_Khi);   cudaGetSymbolAddress((void**)&Klo, g_Klo);
    cudaGetSymbolAddress((void**)&Vthi, g_Vthi); cudaGetSymbolAddress((void**)&Vtlo, g_Vtlo);
    cudaGetSymbolAddress((void**)&Chi, g_Chi);   cudaGetSymbolAddress((void**)&Clo, g_Clo);

    static bool attr_set = false;
    if (!attr_set) {
        cudaFuncSetAttribute(gemm_bf3, cudaFuncAttributeMaxDynamicSharedMemorySize, 4 * 128 * 72 * 2);
        cudaFuncSetAttribute(attn_scores_bf, cudaFuncAttributeMaxDynamicSharedMemorySize, 4 * 128 * 72 * 2);
        cudaFuncSetAttribute(softmax_pv_bf, cudaFuncAttributeMaxDynamicSharedMemorySize,
                             256 * 4 + (2 * 128 * 136 + 2 * 64 * 136) * 2);
        attr_set = true;
    }
    const int gemm_smem  = 4 * 128 * 72 * 2;
    const int fused_smem = 256 * 4 + (2 * 128 * 136 + 2 * 64 * 136) * 2;

    // 1) split inputs + weights into bf16 hi/lo planes
    split_kernel<<<(MROWS * DM / 4 + 255) / 256, 256>>>(q, qhi, qlo, MROWS * DM / 4);
    split_kernel<<<(MROWS * DM / 4 + 255) / 256, 256>>>(k, khi, klo, MROWS * DM / 4);
    split_kernel<<<(MROWS * DM / 4 + 255) / 256, 256>>>(v, vhi, vlo, MROWS * DM / 4);
    split_kernel<<<(DM * DM / 4 + 255) / 256, 256>>>(w_q, wqhi, wqlo, DM * DM / 4);
    split_kernel<<<(DM * DM / 4 + 255) / 256, 256>>>(w_v, wvhi, wvlo, DM * DM / 4);
    split_kernel<<<(DM * DM / 4 + 255) / 256, 256>>>(w_o, wohi, wolo, DM * DM / 4);

    // 2) projections (mode1: split planes; V mode2: transposed split planes)
    dim3 gProj(DM / 128, MROWS / 128);   // (8, 32)
    gemm_bf3<<<gProj, 256, gemm_smem>>>(qhi, qlo, wqhi, wqlo, b_q, MROWS, DM, DM, 1, nullptr, Qhi, Qlo);
    gemm_bf3<<<gProj, 256, gemm_smem>>>(khi, klo, wqhi, wqlo, b_q, MROWS, DM, DM, 1, nullptr, Khi, Klo);
    gemm_bf3<<<gProj, 256, gemm_smem>>>(vhi, vlo, wvhi, wvlo, b_v, MROWS, DM, DM, 2, nullptr, Vthi, Vtlo);

    // 3) masked scaled scores -> attn (raw)
    dim3 gScore(SEQ / 128, SEQ / 128, BATCH * NH);   // (16, 16, 32)
    attn_scores_bf<<<gScore, 256, gemm_smem>>>(Qhi, Qlo, Khi, Klo, mask, attn);

    // 4) fused softmax (in-place normalize of attn) + PV -> Ctx split planes
    dim3 gFused(SEQ / 128, BATCH * NH);              // (16, 32)
    softmax_pv_bf<<<gFused, 256, fused_smem>>>(attn, Vthi, Vtlo, Chi, Clo);

    // 5) output projection -> f32 out
    gemm_bf3<<<gProj, 256, gemm_smem>>>(Chi, Clo, wohi, wolo, b_o, MROWS, DM, DM, 0, out, nullptr, nullptr);
}